// round 13
// baseline (speedup 1.0000x reference)
#include <cuda_runtime.h>
#include <cuda_bf16.h>
#include <cstdint>

// Problem constants
#define BB 4
#define TT 2048
#define CC 1024
#define HH 16
#define DD 64
#define SHARED_D 16
#define PRIV_D 48
#define MM (BB * TT)          // 8192 token rows
#define BH (BB * HH)          // 64 batch-heads
#define GK 1024               // inner K of all projections

// ---------------------------------------------------------------------------
// Scratch (device globals; no allocation allowed)
// ---------------------------------------------------------------------------
__device__ float g_share[MM * SHARED_D];
__device__ float g_q[BH * TT * DD];
__device__ float g_k[BH * TT * DD];
__device__ float g_v[BH * TT * DD];
__device__ float g_y[MM * CC];
// Transposed weights, K-major [N, K]
__device__ float g_WqT[768 * 1024];
__device__ float g_WkT[768 * 1024];
__device__ float g_WvT[1024 * 1024];
__device__ float g_WoT[1024 * 1024];

// ---------------------------------------------------------------------------
// helpers
// ---------------------------------------------------------------------------
static __device__ __forceinline__ uint32_t f2tf32(float x) {
    uint32_t r;
    asm("cvt.rna.tf32.f32 %0, %1;" : "=r"(r) : "f"(x));
    return r;
}
// pack two floats to f16x2: lo in low half, hi in high half
static __device__ __forceinline__ uint32_t pk_f16x2(float lo, float hi) {
    uint32_t r;
    asm("cvt.rn.f16x2.f32 %0, %1, %2;" : "=r"(r) : "f"(hi), "f"(lo));
    return r;
}

#define MMA_TF32(d, a, b) \
    asm volatile("mma.sync.aligned.m16n8k8.row.col.f32.tf32.tf32.f32 " \
                 "{%0,%1,%2,%3}, {%4,%5,%6,%7}, {%8,%9}, {%0,%1,%2,%3};" \
                 : "+f"((d)[0]), "+f"((d)[1]), "+f"((d)[2]), "+f"((d)[3]) \
                 : "r"((a)[0]), "r"((a)[1]), "r"((a)[2]), "r"((a)[3]), \
                   "r"((b)[0]), "r"((b)[1]))

#define MMA_F16(d, a, b) \
    asm volatile("mma.sync.aligned.m16n8k16.row.col.f32.f16.f16.f32 " \
                 "{%0,%1,%2,%3}, {%4,%5,%6,%7}, {%8,%9}, {%0,%1,%2,%3};" \
                 : "+f"((d)[0]), "+f"((d)[1]), "+f"((d)[2]), "+f"((d)[3]) \
                 : "r"((a)[0]), "r"((a)[1]), "r"((a)[2]), "r"((a)[3]), \
                   "r"((b)[0]), "r"((b)[1]))

// ---------------------------------------------------------------------------
// Weight transpose: W [K,N] row-major -> Wt [N,K] row-major
// ---------------------------------------------------------------------------
__global__ void transpose_kernel(const float* __restrict__ W, float* __restrict__ Wt,
                                 int K, int N) {
    __shared__ float tile[32][33];
    int n0 = blockIdx.x * 32, k0 = blockIdx.y * 32;
    int tx = threadIdx.x, ty = threadIdx.y;
    #pragma unroll
    for (int i = 0; i < 4; i++)
        tile[ty + i * 8][tx] = W[(size_t)(k0 + ty + i * 8) * N + n0 + tx];
    __syncthreads();
    #pragma unroll
    for (int i = 0; i < 4; i++)
        Wt[(size_t)(n0 + ty + i * 8) * K + k0 + tx] = tile[tx][ty + i * 8];
}

// ---------------------------------------------------------------------------
// Tensor-core GEMM (mma.sync tf32): C = A[M,1024] @ Bt[N,1024]^T + bias
// mode 0: linear; mode 1: qk-scatter (N=768); mode 2: v-scatter (N=1024)
// ---------------------------------------------------------------------------
#define SMS 36  // smem row stride (floats)

__global__ __launch_bounds__(256) void gemm_tf32mma(const float* __restrict__ A,
                                                    const float* __restrict__ Bt,
                                                    const float* __restrict__ bias,
                                                    float* __restrict__ C, int N,
                                                    int mode)
{
    __shared__ uint32_t As[128 * SMS];
    __shared__ uint32_t Bs[128 * SMS];

    const int tid = threadIdx.x;
    const int wid = tid >> 5, lane = tid & 31;
    const int wm = wid & 1, wn = wid >> 1;
    const int g = lane >> 2, t = lane & 3;
    const int m0 = blockIdx.y * 128, n0 = blockIdx.x * 128;

    float acc[4][4][4] = {};
    float4 ra[4], rb[4];

    #pragma unroll
    for (int l = 0; l < 4; l++) {
        int idx = tid + l * 256;
        int row = idx >> 3, c4 = idx & 7;
        ra[l] = *(const float4*)(A  + (size_t)(m0 + row) * GK + c4 * 4);
        rb[l] = *(const float4*)(Bt + (size_t)(n0 + row) * GK + c4 * 4);
    }

    for (int kc = 0; kc < 32; kc++) {
        __syncthreads();
        #pragma unroll
        for (int l = 0; l < 4; l++) {
            int idx = tid + l * 256;
            int row = idx >> 3, c4 = idx & 7;
            uint4 ua, ub;
            ua.x = f2tf32(ra[l].x); ua.y = f2tf32(ra[l].y);
            ua.z = f2tf32(ra[l].z); ua.w = f2tf32(ra[l].w);
            ub.x = f2tf32(rb[l].x); ub.y = f2tf32(rb[l].y);
            ub.z = f2tf32(rb[l].z); ub.w = f2tf32(rb[l].w);
            *(uint4*)&As[row * SMS + c4 * 4] = ua;
            *(uint4*)&Bs[row * SMS + c4 * 4] = ub;
        }
        __syncthreads();

        if (kc + 1 < 32) {
            #pragma unroll
            for (int l = 0; l < 4; l++) {
                int idx = tid + l * 256;
                int row = idx >> 3, c4 = idx & 7;
                ra[l] = *(const float4*)(A  + (size_t)(m0 + row) * GK + (kc + 1) * 32 + c4 * 4);
                rb[l] = *(const float4*)(Bt + (size_t)(n0 + row) * GK + (kc + 1) * 32 + c4 * 4);
            }
        }

        #pragma unroll
        for (int ks = 0; ks < 4; ks++) {
            uint32_t af[4][4], bf[4][2];
            #pragma unroll
            for (int mt = 0; mt < 4; mt++) {
                int r = wm * 64 + mt * 16 + g;
                int c = ks * 8 + t;
                af[mt][0] = As[r * SMS + c];
                af[mt][1] = As[(r + 8) * SMS + c];
                af[mt][2] = As[r * SMS + c + 4];
                af[mt][3] = As[(r + 8) * SMS + c + 4];
            }
            #pragma unroll
            for (int nt = 0; nt < 4; nt++) {
                int n = wn * 32 + nt * 8 + g;
                int c = ks * 8 + t;
                bf[nt][0] = Bs[n * SMS + c];
                bf[nt][1] = Bs[n * SMS + c + 4];
            }
            #pragma unroll
            for (int mt = 0; mt < 4; mt++)
                #pragma unroll
                for (int nt = 0; nt < 4; nt++)
                    MMA_TF32(acc[mt][nt], af[mt], bf[nt]);
        }
    }

    #pragma unroll
    for (int mt = 0; mt < 4; mt++) {
        int rg0 = m0 + wm * 64 + mt * 16 + g;
        #pragma unroll
        for (int nt = 0; nt < 4; nt++) {
            int cc = n0 + wn * 32 + nt * 8 + 2 * t;
            float2 bi = *(const float2*)(bias + cc);
            float2 o0 = { acc[mt][nt][0] + bi.x, acc[mt][nt][1] + bi.y };
            float2 o1 = { acc[mt][nt][2] + bi.x, acc[mt][nt][3] + bi.y };
            if (mode == 0) {
                *(float2*)(C + (size_t)rg0 * N + cc) = o0;
                *(float2*)(C + (size_t)(rg0 + 8) * N + cc) = o1;
            } else if (mode == 1) {
                int h = cc / PRIV_D, p = cc % PRIV_D;
                int b0 = rg0 >> 11, t0 = rg0 & 2047;
                int b1 = (rg0 + 8) >> 11, t1 = (rg0 + 8) & 2047;
                size_t a0 = (((size_t)(b0 * HH + h) * TT + t0) * DD) + SHARED_D + p;
                size_t a1 = (((size_t)(b1 * HH + h) * TT + t1) * DD) + SHARED_D + p;
                *(float2*)(C + a0) = o0;
                *(float2*)(C + a1) = o1;
            } else {
                int h = cc >> 6, d = cc & 63;
                int b0 = rg0 >> 11, t0 = rg0 & 2047;
                int b1 = (rg0 + 8) >> 11, t1 = (rg0 + 8) & 2047;
                size_t a0 = (((size_t)(b0 * HH + h) * TT + t0) * DD) + d;
                size_t a1 = (((size_t)(b1 * HH + h) * TT + t1) * DD) + d;
                *(float2*)(C + a0) = o0;
                *(float2*)(C + a1) = o1;
            }
        }
    }
}

// ---------------------------------------------------------------------------
// SIMT GEMM (tiny N=16 shared projection) -> g_share [MM,16]
// ---------------------------------------------------------------------------
__global__ void gemm_bias_kernel(const float* __restrict__ A,
                                 const float* __restrict__ W,
                                 const float* __restrict__ bias,
                                 float* __restrict__ C,
                                 int M, int N, int K)
{
    const int TM = 64, TN = 64, TK = 16;
    __shared__ float Asm[TK][TM];
    __shared__ float Wsm[TK][TN];

    int tid = threadIdx.x;
    int tx = tid & 15;
    int ty = tid >> 4;
    int m0 = blockIdx.y * TM;
    int n0 = blockIdx.x * TN;

    float acc[4][4] = {};

    for (int k0 = 0; k0 < K; k0 += TK) {
        #pragma unroll
        for (int l = 0; l < 4; l++) {
            int idx = tid + l * 256;
            int mi = idx >> 4;
            int ki = idx & 15;
            Asm[ki][mi] = A[(size_t)(m0 + mi) * K + (k0 + ki)];
        }
        #pragma unroll
        for (int l = 0; l < 4; l++) {
            int idx = tid + l * 256;
            int ki = idx >> 6;
            int ni = idx & 63;
            int gn = n0 + ni;
            Wsm[ki][ni] = (gn < N) ? W[(size_t)(k0 + ki) * N + gn] : 0.f;
        }
        __syncthreads();

        #pragma unroll
        for (int kk = 0; kk < TK; kk++) {
            float4 a4 = *reinterpret_cast<const float4*>(&Asm[kk][ty * 4]);
            float4 w4 = *reinterpret_cast<const float4*>(&Wsm[kk][tx * 4]);
            float a[4] = {a4.x, a4.y, a4.z, a4.w};
            float w[4] = {w4.x, w4.y, w4.z, w4.w};
            #pragma unroll
            for (int i = 0; i < 4; i++)
                #pragma unroll
                for (int j = 0; j < 4; j++)
                    acc[i][j] = fmaf(a[i], w[j], acc[i][j]);
        }
        __syncthreads();
    }

    #pragma unroll
    for (int i = 0; i < 4; i++) {
        int gm = m0 + ty * 4 + i;
        #pragma unroll
        for (int j = 0; j < 4; j++) {
            int gn = n0 + tx * 4 + j;
            if (gn < N)
                C[(size_t)gm * N + gn] = acc[i][j] + bias[gn];
        }
    }
}

// ---------------------------------------------------------------------------
// Broadcast the 16 shared dims into all heads of g_q and g_k.
// ---------------------------------------------------------------------------
__global__ void broadcast_share_kernel()
{
    int idx = blockIdx.x * blockDim.x + threadIdx.x;   // 0 .. 524287
    int c4 = idx & 3;
    int t = (idx >> 2) & (TT - 1);
    int h = (idx >> 13) & (HH - 1);
    int b = idx >> 17;
    size_t row = (size_t)b * TT + t;
    float4 s = *(const float4*)(g_share + row * SHARED_D + c4 * 4);
    size_t dst = (((size_t)(b * HH + h) * TT + t) * DD) + c4 * 4;
    *(float4*)(g_q + dst) = s;
    *(float4*)(g_k + dst) = s;
    (void)h;
}

// ---------------------------------------------------------------------------
// Flash attention: S via tf32 mma, PV via f16 m16n8k16 with P in registers.
// fp16 mantissa (10 bits) == tf32 mantissa, so numerics match the tf32-PV
// version (R9: 5.17e-4), unlike bf16 (8 bits -> 2e-3, failed).
// CTA: 128 q-rows x 64 kv-cols per iter. 8 warps, 16 rows each.
// grid = (T/128, B*H), block = 256. smem = 60 KB.
// ---------------------------------------------------------------------------
#define FAS 68   // Q/K smem row stride (u32)
#define VPS 72   // Vp smem row stride (u32) — 72 mod 32 = 8 -> conflict-free

__global__ __launch_bounds__(256) void flash_attn_mma()
{
    extern __shared__ uint32_t fsm[];
    uint32_t* Qs = fsm;                    // 128*68 (tf32)
    uint32_t* Ks = Qs + 128 * FAS;         // 64*68  (tf32)
    uint32_t* Vp = Ks + 64 * FAS;          // 32*72  (f16x2 pairs: rows 2jp,2jp+1)

    const int mb  = blockIdx.x;
    const int bh  = blockIdx.y;
    const int tid = threadIdx.x;
    const int w   = tid >> 5, lane = tid & 31;
    const int g   = lane >> 2, t = lane & 3;
    const size_t base = (size_t)bh * TT * DD;
    const float scale = 0.125f;   // folded into Q

    // Load Q tile [128, 64] as tf32, pre-scaled
    #pragma unroll
    for (int l = 0; l < 8; l++) {
        int idx = tid + l * 256;
        int i = idx >> 4, d4 = idx & 15;
        float4 v = *(const float4*)(g_q + base + (size_t)(mb * 128 + i) * DD + d4 * 4);
        uint32_t* p = &Qs[i * FAS + d4 * 4];
        p[0] = f2tf32(v.x * scale); p[1] = f2tf32(v.y * scale);
        p[2] = f2tf32(v.z * scale); p[3] = f2tf32(v.w * scale);
    }

    const int r0 = w * 16 + g;
    const int gr0 = mb * 128 + r0;
    const int gr1 = gr0 + 8;
    const int wrow_max = mb * 128 + w * 16 + 15;

    float m0s = -1e30f, m1s = -1e30f, l0s = 0.f, l1s = 0.f;
    float acc_o[8][4] = {};

    const int jb_max = 2 * mb + 1;
    for (int jb = 0; jb <= jb_max; jb++) {
        __syncthreads();   // everyone done reading previous Ks/Vp

        // K: [64,64] -> tf32 row-major (4 items/thread)
        #pragma unroll
        for (int l = 0; l < 4; l++) {
            int idx = tid + l * 256;
            int j = idx >> 4, d4 = idx & 15;
            float4 kv = *(const float4*)(g_k + base + (size_t)(jb * 64 + j) * DD + d4 * 4);
            uint32_t* kp = &Ks[j * FAS + d4 * 4];
            kp[0] = f2tf32(kv.x); kp[1] = f2tf32(kv.y);
            kp[2] = f2tf32(kv.z); kp[3] = f2tf32(kv.w);
        }
        // V: pack f16x2 pairs Vp[jp][d] = {v[2jp][d] lo, v[2jp+1][d] hi} (2 items/thread)
        #pragma unroll
        for (int l = 0; l < 2; l++) {
            int item = tid + l * 256;      // 0..511
            int jp = item >> 4;            // 0..31
            int d4 = item & 15;            // 0..15
            size_t ga = base + (size_t)(jb * 64 + 2 * jp) * DD + d4 * 4;
            float4 v0 = *(const float4*)(g_v + ga);
            float4 v1 = *(const float4*)(g_v + ga + DD);
            uint4 pk;
            pk.x = pk_f16x2(v0.x, v1.x);
            pk.y = pk_f16x2(v0.y, v1.y);
            pk.z = pk_f16x2(v0.z, v1.z);
            pk.w = pk_f16x2(v0.w, v1.w);
            *(uint4*)&Vp[jp * VPS + d4 * 4] = pk;
        }
        __syncthreads();

        if (jb * 64 > wrow_max) continue;    // block fully above this warp's rows

        // S = Q @ K^T  (warp: 16 rows x 64 cols), tf32
        float s[8][4] = {};
        #pragma unroll
        for (int ks = 0; ks < 8; ks++) {
            uint32_t a[4];
            a[0] = Qs[r0 * FAS + ks * 8 + t];
            a[1] = Qs[(r0 + 8) * FAS + ks * 8 + t];
            a[2] = Qs[r0 * FAS + ks * 8 + t + 4];
            a[3] = Qs[(r0 + 8) * FAS + ks * 8 + t + 4];
            #pragma unroll
            for (int nt = 0; nt < 8; nt++) {
                uint32_t b[2];
                b[0] = Ks[(nt * 8 + g) * FAS + ks * 8 + t];
                b[1] = Ks[(nt * 8 + g) * FAS + ks * 8 + t + 4];
                MMA_TF32(s[nt], a, b);
            }
        }

        // causal mask (Q pre-scaled)
        #pragma unroll
        for (int nt = 0; nt < 8; nt++) {
            int c0 = jb * 64 + nt * 8 + 2 * t;
            s[nt][0] = (c0     <= gr0) ? s[nt][0] : -1e30f;
            s[nt][1] = (c0 + 1 <= gr0) ? s[nt][1] : -1e30f;
            s[nt][2] = (c0     <= gr1) ? s[nt][2] : -1e30f;
            s[nt][3] = (c0 + 1 <= gr1) ? s[nt][3] : -1e30f;
        }

        // row max (local + 4-lane shuffle over t-group)
        float mx0 = -1e30f, mx1 = -1e30f;
        #pragma unroll
        for (int nt = 0; nt < 8; nt++) {
            mx0 = fmaxf(mx0, fmaxf(s[nt][0], s[nt][1]));
            mx1 = fmaxf(mx1, fmaxf(s[nt][2], s[nt][3]));
        }
        mx0 = fmaxf(mx0, __shfl_xor_sync(0xffffffff, mx0, 1));
        mx0 = fmaxf(mx0, __shfl_xor_sync(0xffffffff, mx0, 2));
        mx1 = fmaxf(mx1, __shfl_xor_sync(0xffffffff, mx1, 1));
        mx1 = fmaxf(mx1, __shfl_xor_sync(0xffffffff, mx1, 2));

        float mn0 = fmaxf(m0s, mx0), mn1 = fmaxf(m1s, mx1);
        float al0 = __expf(m0s - mn0), al1 = __expf(m1s - mn1);
        m0s = mn0; m1s = mn1;

        // exp + pack P into f16 A-fragments (m16n8k16): chunk c covers nt=2c,2c+1
        uint32_t pb[4][4];
        float sum0 = 0.f, sum1 = 0.f;
        #pragma unroll
        for (int nt = 0; nt < 8; nt++) {
            float p0 = __expf(s[nt][0] - mn0);
            float p1 = __expf(s[nt][1] - mn0);
            float p2 = __expf(s[nt][2] - mn1);
            float p3 = __expf(s[nt][3] - mn1);
            sum0 += p0 + p1; sum1 += p2 + p3;
            int c = nt >> 1;
            if ((nt & 1) == 0) {
                pb[c][0] = pk_f16x2(p0, p1);   // (g,   16c+2t / +1)
                pb[c][1] = pk_f16x2(p2, p3);   // (g+8, 16c+2t / +1)
            } else {
                pb[c][2] = pk_f16x2(p0, p1);   // (g,   16c+8+2t / +1)
                pb[c][3] = pk_f16x2(p2, p3);   // (g+8, 16c+8+2t / +1)
            }
        }
        sum0 += __shfl_xor_sync(0xffffffff, sum0, 1);
        sum0 += __shfl_xor_sync(0xffffffff, sum0, 2);
        sum1 += __shfl_xor_sync(0xffffffff, sum1, 1);
        sum1 += __shfl_xor_sync(0xffffffff, sum1, 2);
        l0s = l0s * al0 + sum0;
        l1s = l1s * al1 + sum1;

        #pragma unroll
        for (int nt = 0; nt < 8; nt++) {
            acc_o[nt][0] *= al0; acc_o[nt][1] *= al0;
            acc_o[nt][2] *= al1; acc_o[nt][3] *= al1;
        }

        // O += P @ V : f16 m16n8k16, P from registers, V from Vp
        #pragma unroll
        for (int c = 0; c < 4; c++) {
            #pragma unroll
            for (int nt = 0; nt < 8; nt++) {
                uint32_t b[2];
                b[0] = Vp[(8 * c + t) * VPS + nt * 8 + g];       // k rows 16c+2t,+1
                b[1] = Vp[(8 * c + 4 + t) * VPS + nt * 8 + g];   // k rows 16c+8+2t,+1
                MMA_F16(acc_o[nt], pb[c], b);
            }
        }
    }

    // Epilogue: y[b, row, h*64 + d]
    const int h = bh & (HH - 1);
    const int b = bh >> 4;
    const float inv0 = 1.f / l0s, inv1 = 1.f / l1s;
    size_t row0 = (size_t)b * TT + mb * 128 + r0;
    #pragma unroll
    for (int nt = 0; nt < 8; nt++) {
        int col = h * DD + nt * 8 + 2 * t;
        float2 o0 = { acc_o[nt][0] * inv0, acc_o[nt][1] * inv0 };
        float2 o1 = { acc_o[nt][2] * inv1, acc_o[nt][3] * inv1 };
        *(float2*)(g_y + row0 * CC + col) = o0;
        *(float2*)(g_y + (row0 + 8) * CC + col) = o1;
    }
}

// ---------------------------------------------------------------------------
// Launch
// ---------------------------------------------------------------------------
extern "C" void kernel_launch(void* const* d_in, const int* in_sizes, int n_in,
                              void* d_out, int out_size)
{
    const float* x       = (const float*)d_in[0];
    const float* W_share = (const float*)d_in[1];
    const float* b_share = (const float*)d_in[2];
    const float* Wq      = (const float*)d_in[3];
    const float* bq      = (const float*)d_in[4];
    const float* Wk      = (const float*)d_in[5];
    const float* bk      = (const float*)d_in[6];
    const float* Wv      = (const float*)d_in[7];
    const float* bv      = (const float*)d_in[8];
    const float* Wo      = (const float*)d_in[9];
    const float* bo      = (const float*)d_in[10];
    float* out = (float*)d_out;

    float *p_share, *p_q, *p_k, *p_v, *p_y;
    float *p_WqT, *p_WkT, *p_WvT, *p_WoT;
    cudaGetSymbolAddress((void**)&p_share, g_share);
    cudaGetSymbolAddress((void**)&p_q, g_q);
    cudaGetSymbolAddress((void**)&p_k, g_k);
    cudaGetSymbolAddress((void**)&p_v, g_v);
    cudaGetSymbolAddress((void**)&p_y, g_y);
    cudaGetSymbolAddress((void**)&p_WqT, g_WqT);
    cudaGetSymbolAddress((void**)&p_WkT, g_WkT);
    cudaGetSymbolAddress((void**)&p_WvT, g_WvT);
    cudaGetSymbolAddress((void**)&p_WoT, g_WoT);

    dim3 blk(256);
    dim3 tblk(32, 8);

    // Weight transposes (K-major B operand for mma row.col)
    transpose_kernel<<<dim3(768 / 32, 1024 / 32), tblk>>>(Wq, p_WqT, 1024, 768);
    transpose_kernel<<<dim3(768 / 32, 1024 / 32), tblk>>>(Wk, p_WkT, 1024, 768);
    transpose_kernel<<<dim3(1024 / 32, 1024 / 32), tblk>>>(Wv, p_WvT, 1024, 1024);
    transpose_kernel<<<dim3(1024 / 32, 1024 / 32), tblk>>>(Wo, p_WoT, 1024, 1024);

    // Shared projection (SIMT, N=16) -> g_share
    gemm_bias_kernel<<<dim3(1, MM / 64), blk>>>(x, W_share, b_share, p_share,
                                                MM, SHARED_D, CC);

    // Broadcast shared dims into q/k head layout
    broadcast_share_kernel<<<(BH * TT * 4) / 256, blk>>>();

    // Tensor-core projections with fused scatter epilogues
    gemm_tf32mma<<<dim3(6, MM / 128), blk>>>(x, p_WqT, bq, p_q, 768, 1);
    gemm_tf32mma<<<dim3(6, MM / 128), blk>>>(x, p_WkT, bk, p_k, 768, 1);
    gemm_tf32mma<<<dim3(8, MM / 128), blk>>>(x, p_WvT, bv, p_v, 1024, 2);

    // Flash attention (tf32 QK + f16 PV, P register-resident)
    const int FA_SMEM = (128 * FAS + 64 * FAS + 32 * VPS) * 4;  // 61440
    cudaFuncSetAttribute(flash_attn_mma, cudaFuncAttributeMaxDynamicSharedMemorySize, FA_SMEM);
    flash_attn_mma<<<dim3(TT / 128, BH), blk, FA_SMEM>>>();

    // Output projection (linear epilogue)
    gemm_tf32mma<<<dim3(8, MM / 128), blk>>>(p_y, p_WoT, bo, out, 1024, 0);

    (void)in_sizes; (void)n_in; (void)out_size;
}

// round 15
// speedup vs baseline: 1.5081x; 1.5081x over previous
#include <cuda_runtime.h>
#include <cuda_bf16.h>
#include <cstdint>

// Problem constants
#define BB 4
#define TT 2048
#define CC 1024
#define HH 16
#define DD 64
#define SHARED_D 16
#define PRIV_D 48
#define MM (BB * TT)          // 8192 token rows
#define BH (BB * HH)          // 64 batch-heads
#define GK 1024               // inner K of all projections

// ---------------------------------------------------------------------------
// Scratch (device globals; no allocation allowed)
// ---------------------------------------------------------------------------
__device__ float g_share[MM * SHARED_D];
__device__ float g_q[BH * TT * DD];   // tf32-rounded, pre-scaled by 0.125
__device__ float g_k[BH * TT * DD];   // tf32-rounded
__device__ float g_v[BH * TT * DD];   // fp32
__device__ float g_y[MM * CC];
// Transposed weights, K-major [N, K]
__device__ float g_WqT[768 * 1024];
__device__ float g_WkT[768 * 1024];
__device__ float g_WvT[1024 * 1024];
__device__ float g_WoT[1024 * 1024];

// ---------------------------------------------------------------------------
// helpers
// ---------------------------------------------------------------------------
static __device__ __forceinline__ uint32_t f2tf32(float x) {
    uint32_t r;
    asm("cvt.rna.tf32.f32 %0, %1;" : "=r"(r) : "f"(x));
    return r;
}
// pack two floats to f16x2: lo in low half, hi in high half
static __device__ __forceinline__ uint32_t pk_f16x2(float lo, float hi) {
    uint32_t r;
    asm("cvt.rn.f16x2.f32 %0, %1, %2;" : "=r"(r) : "f"(hi), "f"(lo));
    return r;
}
static __device__ __forceinline__ uint32_t smem_u32(const void* p) {
    uint32_t a;
    asm("{ .reg .u64 t; cvta.to.shared.u64 t, %1; cvt.u32.u64 %0, t; }"
        : "=r"(a) : "l"(p));
    return a;
}
static __device__ __forceinline__ void cp_async16(uint32_t dst_smem, const void* src) {
    asm volatile("cp.async.ca.shared.global [%0], [%1], 16;"
                 :: "r"(dst_smem), "l"(src) : "memory");
}
#define CP_COMMIT() asm volatile("cp.async.commit_group;" ::: "memory")
#define CP_WAIT0()  asm volatile("cp.async.wait_group 0;" ::: "memory")

#define MMA_TF32(d, a, b) \
    asm volatile("mma.sync.aligned.m16n8k8.row.col.f32.tf32.tf32.f32 " \
                 "{%0,%1,%2,%3}, {%4,%5,%6,%7}, {%8,%9}, {%0,%1,%2,%3};" \
                 : "+f"((d)[0]), "+f"((d)[1]), "+f"((d)[2]), "+f"((d)[3]) \
                 : "r"((a)[0]), "r"((a)[1]), "r"((a)[2]), "r"((a)[3]), \
                   "r"((b)[0]), "r"((b)[1]))

#define MMA_F16(d, a, b) \
    asm volatile("mma.sync.aligned.m16n8k16.row.col.f32.f16.f16.f32 " \
                 "{%0,%1,%2,%3}, {%4,%5,%6,%7}, {%8,%9}, {%0,%1,%2,%3};" \
                 : "+f"((d)[0]), "+f"((d)[1]), "+f"((d)[2]), "+f"((d)[3]) \
                 : "r"((a)[0]), "r"((a)[1]), "r"((a)[2]), "r"((a)[3]), \
                   "r"((b)[0]), "r"((b)[1]))

// ---------------------------------------------------------------------------
// Weight transpose: W [K,N] row-major -> Wt [N,K] row-major
// ---------------------------------------------------------------------------
__global__ void transpose_kernel(const float* __restrict__ W, float* __restrict__ Wt,
                                 int K, int N) {
    __shared__ float tile[32][33];
    int n0 = blockIdx.x * 32, k0 = blockIdx.y * 32;
    int tx = threadIdx.x, ty = threadIdx.y;
    #pragma unroll
    for (int i = 0; i < 4; i++)
        tile[ty + i * 8][tx] = W[(size_t)(k0 + ty + i * 8) * N + n0 + tx];
    __syncthreads();
    #pragma unroll
    for (int i = 0; i < 4; i++)
        Wt[(size_t)(n0 + ty + i * 8) * K + k0 + tx] = tile[tx][ty + i * 8];
}

// ---------------------------------------------------------------------------
// Tensor-core GEMM (mma.sync tf32): C = A[M,1024] @ Bt[N,1024]^T + bias
// mode 0: linear row-major [M, N]
// mode 1: k-scatter  (N=768), tf32-rounded
// mode 2: v-scatter  (N=1024), fp32
// mode 3: q-scatter  (N=768), scaled by 0.125 then tf32-rounded
// ---------------------------------------------------------------------------
#define SMS 36  // smem row stride (floats)

__global__ __launch_bounds__(256) void gemm_tf32mma(const float* __restrict__ A,
                                                    const float* __restrict__ Bt,
                                                    const float* __restrict__ bias,
                                                    float* __restrict__ C, int N,
                                                    int mode)
{
    __shared__ uint32_t As[128 * SMS];
    __shared__ uint32_t Bs[128 * SMS];

    const int tid = threadIdx.x;
    const int wid = tid >> 5, lane = tid & 31;
    const int wm = wid & 1, wn = wid >> 1;
    const int g = lane >> 2, t = lane & 3;
    const int m0 = blockIdx.y * 128, n0 = blockIdx.x * 128;

    float acc[4][4][4] = {};
    float4 ra[4], rb[4];

    #pragma unroll
    for (int l = 0; l < 4; l++) {
        int idx = tid + l * 256;
        int row = idx >> 3, c4 = idx & 7;
        ra[l] = *(const float4*)(A  + (size_t)(m0 + row) * GK + c4 * 4);
        rb[l] = *(const float4*)(Bt + (size_t)(n0 + row) * GK + c4 * 4);
    }

    for (int kc = 0; kc < 32; kc++) {
        __syncthreads();
        #pragma unroll
        for (int l = 0; l < 4; l++) {
            int idx = tid + l * 256;
            int row = idx >> 3, c4 = idx & 7;
            uint4 ua, ub;
            ua.x = f2tf32(ra[l].x); ua.y = f2tf32(ra[l].y);
            ua.z = f2tf32(ra[l].z); ua.w = f2tf32(ra[l].w);
            ub.x = f2tf32(rb[l].x); ub.y = f2tf32(rb[l].y);
            ub.z = f2tf32(rb[l].z); ub.w = f2tf32(rb[l].w);
            *(uint4*)&As[row * SMS + c4 * 4] = ua;
            *(uint4*)&Bs[row * SMS + c4 * 4] = ub;
        }
        __syncthreads();

        if (kc + 1 < 32) {
            #pragma unroll
            for (int l = 0; l < 4; l++) {
                int idx = tid + l * 256;
                int row = idx >> 3, c4 = idx & 7;
                ra[l] = *(const float4*)(A  + (size_t)(m0 + row) * GK + (kc + 1) * 32 + c4 * 4);
                rb[l] = *(const float4*)(Bt + (size_t)(n0 + row) * GK + (kc + 1) * 32 + c4 * 4);
            }
        }

        #pragma unroll
        for (int ks = 0; ks < 4; ks++) {
            uint32_t af[4][4], bf[4][2];
            #pragma unroll
            for (int mt = 0; mt < 4; mt++) {
                int r = wm * 64 + mt * 16 + g;
                int c = ks * 8 + t;
                af[mt][0] = As[r * SMS + c];
                af[mt][1] = As[(r + 8) * SMS + c];
                af[mt][2] = As[r * SMS + c + 4];
                af[mt][3] = As[(r + 8) * SMS + c + 4];
            }
            #pragma unroll
            for (int nt = 0; nt < 4; nt++) {
                int n = wn * 32 + nt * 8 + g;
                int c = ks * 8 + t;
                bf[nt][0] = Bs[n * SMS + c];
                bf[nt][1] = Bs[n * SMS + c + 4];
            }
            #pragma unroll
            for (int mt = 0; mt < 4; mt++)
                #pragma unroll
                for (int nt = 0; nt < 4; nt++)
                    MMA_TF32(acc[mt][nt], af[mt], bf[nt]);
        }
    }

    #pragma unroll
    for (int mt = 0; mt < 4; mt++) {
        int rg0 = m0 + wm * 64 + mt * 16 + g;
        #pragma unroll
        for (int nt = 0; nt < 4; nt++) {
            int cc = n0 + wn * 32 + nt * 8 + 2 * t;
            float2 bi = *(const float2*)(bias + cc);
            float2 o0 = { acc[mt][nt][0] + bi.x, acc[mt][nt][1] + bi.y };
            float2 o1 = { acc[mt][nt][2] + bi.x, acc[mt][nt][3] + bi.y };
            if (mode == 0) {
                *(float2*)(C + (size_t)rg0 * N + cc) = o0;
                *(float2*)(C + (size_t)(rg0 + 8) * N + cc) = o1;
            } else if (mode == 2) {
                int h = cc >> 6, d = cc & 63;
                int b0 = rg0 >> 11, t0 = rg0 & 2047;
                int b1 = (rg0 + 8) >> 11, t1 = (rg0 + 8) & 2047;
                size_t a0 = (((size_t)(b0 * HH + h) * TT + t0) * DD) + d;
                size_t a1 = (((size_t)(b1 * HH + h) * TT + t1) * DD) + d;
                *(float2*)(C + a0) = o0;
                *(float2*)(C + a1) = o1;
            } else {  // mode 1 (k) or 3 (q): scatter + tf32 round (+scale for q)
                if (mode == 3) {
                    o0.x *= 0.125f; o0.y *= 0.125f;
                    o1.x *= 0.125f; o1.y *= 0.125f;
                }
                o0.x = __uint_as_float(f2tf32(o0.x));
                o0.y = __uint_as_float(f2tf32(o0.y));
                o1.x = __uint_as_float(f2tf32(o1.x));
                o1.y = __uint_as_float(f2tf32(o1.y));
                int h = cc / PRIV_D, p = cc % PRIV_D;
                int b0 = rg0 >> 11, t0 = rg0 & 2047;
                int b1 = (rg0 + 8) >> 11, t1 = (rg0 + 8) & 2047;
                size_t a0 = (((size_t)(b0 * HH + h) * TT + t0) * DD) + SHARED_D + p;
                size_t a1 = (((size_t)(b1 * HH + h) * TT + t1) * DD) + SHARED_D + p;
                *(float2*)(C + a0) = o0;
                *(float2*)(C + a1) = o1;
            }
        }
    }
}

// ---------------------------------------------------------------------------
// SIMT GEMM (tiny N=16 shared projection) -> g_share [MM,16]
// ---------------------------------------------------------------------------
__global__ void gemm_bias_kernel(const float* __restrict__ A,
                                 const float* __restrict__ W,
                                 const float* __restrict__ bias,
                                 float* __restrict__ C,
                                 int M, int N, int K)
{
    const int TM = 64, TN = 64, TK = 16;
    __shared__ float Asm[TK][TM];
    __shared__ float Wsm[TK][TN];

    int tid = threadIdx.x;
    int tx = tid & 15;
    int ty = tid >> 4;
    int m0 = blockIdx.y * TM;
    int n0 = blockIdx.x * TN;

    float acc[4][4] = {};

    for (int k0 = 0; k0 < K; k0 += TK) {
        #pragma unroll
        for (int l = 0; l < 4; l++) {
            int idx = tid + l * 256;
            int mi = idx >> 4;
            int ki = idx & 15;
            Asm[ki][mi] = A[(size_t)(m0 + mi) * K + (k0 + ki)];
        }
        #pragma unroll
        for (int l = 0; l < 4; l++) {
            int idx = tid + l * 256;
            int ki = idx >> 6;
            int ni = idx & 63;
            int gn = n0 + ni;
            Wsm[ki][ni] = (gn < N) ? W[(size_t)(k0 + ki) * N + gn] : 0.f;
        }
        __syncthreads();

        #pragma unroll
        for (int kk = 0; kk < TK; kk++) {
            float4 a4 = *reinterpret_cast<const float4*>(&Asm[kk][ty * 4]);
            float4 w4 = *reinterpret_cast<const float4*>(&Wsm[kk][tx * 4]);
            float a[4] = {a4.x, a4.y, a4.z, a4.w};
            float w[4] = {w4.x, w4.y, w4.z, w4.w};
            #pragma unroll
            for (int i = 0; i < 4; i++)
                #pragma unroll
                for (int j = 0; j < 4; j++)
                    acc[i][j] = fmaf(a[i], w[j], acc[i][j]);
        }
        __syncthreads();
    }

    #pragma unroll
    for (int i = 0; i < 4; i++) {
        int gm = m0 + ty * 4 + i;
        #pragma unroll
        for (int j = 0; j < 4; j++) {
            int gn = n0 + tx * 4 + j;
            if (gn < N)
                C[(size_t)gm * N + gn] = acc[i][j] + bias[gn];
        }
    }
}

// ---------------------------------------------------------------------------
// Broadcast the 16 shared dims into all heads of g_q (scaled+rounded) and
// g_k (rounded).
// ---------------------------------------------------------------------------
__global__ void broadcast_share_kernel()
{
    int idx = blockIdx.x * blockDim.x + threadIdx.x;   // 0 .. 524287
    int c4 = idx & 3;
    int t = (idx >> 2) & (TT - 1);
    int h = (idx >> 13) & (HH - 1);
    int b = idx >> 17;
    size_t row = (size_t)b * TT + t;
    float4 s = *(const float4*)(g_share + row * SHARED_D + c4 * 4);
    float4 q, k;
    q.x = __uint_as_float(f2tf32(s.x * 0.125f));
    q.y = __uint_as_float(f2tf32(s.y * 0.125f));
    q.z = __uint_as_float(f2tf32(s.z * 0.125f));
    q.w = __uint_as_float(f2tf32(s.w * 0.125f));
    k.x = __uint_as_float(f2tf32(s.x));
    k.y = __uint_as_float(f2tf32(s.y));
    k.z = __uint_as_float(f2tf32(s.z));
    k.w = __uint_as_float(f2tf32(s.w));
    size_t dst = (((size_t)(b * HH + h) * TT + t) * DD) + c4 * 4;
    *(float4*)(g_q + dst) = q;
    *(float4*)(g_k + dst) = k;
    (void)h;
}

// ---------------------------------------------------------------------------
// Flash attention: tf32 QK mma + f16 PV mma (P register-resident).
// Double-buffered K (cp.async) and V (f16-pack) stages; ONE sync per KV block.
// g_q/g_k already tf32-rounded (Q pre-scaled) -> raw byte copies.
// CTA: 128 q-rows x 64 kv-cols. 8 warps, 16 rows each. smem = 86 KB.
// ---------------------------------------------------------------------------
#define FAS 68   // Q/K smem row stride (u32)
#define VPS 72   // Vp smem row stride (u32)

static __device__ __forceinline__ void load_pack_v(size_t base, int jb,
                                                   uint32_t* dst, int tid) {
    #pragma unroll
    for (int l = 0; l < 2; l++) {
        int item = tid + l * 256;      // 0..511
        int jp = item >> 4;            // 0..31
        int d4 = item & 15;            // 0..15
        size_t ga = base + (size_t)(jb * 64 + 2 * jp) * DD + d4 * 4;
        float4 v0 = *(const float4*)(g_v + ga);
        float4 v1 = *(const float4*)(g_v + ga + DD);
        uint4 pk;
        pk.x = pk_f16x2(v0.x, v1.x);
        pk.y = pk_f16x2(v0.y, v1.y);
        pk.z = pk_f16x2(v0.z, v1.z);
        pk.w = pk_f16x2(v0.w, v1.w);
        *(uint4*)&dst[jp * VPS + d4 * 4] = pk;
    }
}

__global__ __launch_bounds__(256) void flash_attn_mma()
{
    extern __shared__ uint32_t fsm[];
    uint32_t* Qs  = fsm;                    // 128*68
    uint32_t* Ks0 = fsm + 128 * FAS;        // 64*68
    uint32_t* Ks1 = Ks0 + 64 * FAS;         // 64*68
    uint32_t* Vp0 = Ks1 + 64 * FAS;         // 32*72
    uint32_t* Vp1 = Vp0 + 32 * VPS;         // 32*72

    const int mb  = blockIdx.x;
    const int bh  = blockIdx.y;
    const int tid = threadIdx.x;
    const int w   = tid >> 5, lane = tid & 31;
    const int g   = lane >> 2, t = lane & 3;
    const size_t base = (size_t)bh * TT * DD;

    const uint32_t qs_s  = smem_u32(Qs);
    const uint32_t ks_s0 = smem_u32(Ks0);
    const uint32_t ks_s1 = smem_u32(Ks1);

    // Prologue: Q (raw, pre-scaled+rounded) + K block 0 via cp.async; V block 0 packed
    #pragma unroll
    for (int l = 0; l < 8; l++) {
        int idx = tid + l * 256;
        int i = idx >> 4, d4 = idx & 15;
        cp_async16(qs_s + (i * FAS + d4 * 4) * 4,
                   g_q + base + (size_t)(mb * 128 + i) * DD + d4 * 4);
    }
    #pragma unroll
    for (int l = 0; l < 4; l++) {
        int idx = tid + l * 256;
        int j = idx >> 4, d4 = idx & 15;
        cp_async16(ks_s0 + (j * FAS + d4 * 4) * 4,
                   g_k + base + (size_t)j * DD + d4 * 4);
    }
    CP_COMMIT();
    load_pack_v(base, 0, Vp0, tid);
    CP_WAIT0();
    __syncthreads();

    const int r0 = w * 16 + g;
    const int gr0 = mb * 128 + r0;
    const int gr1 = gr0 + 8;
    const int wrow_max = mb * 128 + w * 16 + 15;

    float m0s = -1e30f, m1s = -1e30f, l0s = 0.f, l1s = 0.f;
    float acc_o[8][4] = {};

    const int jb_max = 2 * mb + 1;
    for (int jb = 0; jb <= jb_max; jb++) {
        const int s = jb & 1;
        // Prefetch next K (async) and V (sync pack) into the other stage
        if (jb < jb_max) {
            uint32_t kd = s ? ks_s0 : ks_s1;
            #pragma unroll
            for (int l = 0; l < 4; l++) {
                int idx = tid + l * 256;
                int j = idx >> 4, d4 = idx & 15;
                cp_async16(kd + (j * FAS + d4 * 4) * 4,
                           g_k + base + (size_t)((jb + 1) * 64 + j) * DD + d4 * 4);
            }
            CP_COMMIT();
            load_pack_v(base, jb + 1, s ? Vp0 : Vp1, tid);
        }

        if (jb * 64 <= wrow_max) {
            const uint32_t* Kc = s ? Ks1 : Ks0;
            const uint32_t* Vc = s ? Vp1 : Vp0;

            // S = Q @ K^T  (warp: 16 rows x 64 cols), tf32
            float sacc[8][4] = {};
            #pragma unroll
            for (int ks = 0; ks < 8; ks++) {
                uint32_t a[4];
                a[0] = Qs[r0 * FAS + ks * 8 + t];
                a[1] = Qs[(r0 + 8) * FAS + ks * 8 + t];
                a[2] = Qs[r0 * FAS + ks * 8 + t + 4];
                a[3] = Qs[(r0 + 8) * FAS + ks * 8 + t + 4];
                #pragma unroll
                for (int nt = 0; nt < 8; nt++) {
                    uint32_t b[2];
                    b[0] = Kc[(nt * 8 + g) * FAS + ks * 8 + t];
                    b[1] = Kc[(nt * 8 + g) * FAS + ks * 8 + t + 4];
                    MMA_TF32(sacc[nt], a, b);
                }
            }

            // causal mask (Q pre-scaled upstream)
            #pragma unroll
            for (int nt = 0; nt < 8; nt++) {
                int c0 = jb * 64 + nt * 8 + 2 * t;
                sacc[nt][0] = (c0     <= gr0) ? sacc[nt][0] : -1e30f;
                sacc[nt][1] = (c0 + 1 <= gr0) ? sacc[nt][1] : -1e30f;
                sacc[nt][2] = (c0     <= gr1) ? sacc[nt][2] : -1e30f;
                sacc[nt][3] = (c0 + 1 <= gr1) ? sacc[nt][3] : -1e30f;
            }

            // row max (local + 4-lane shuffle over t-group)
            float mx0 = -1e30f, mx1 = -1e30f;
            #pragma unroll
            for (int nt = 0; nt < 8; nt++) {
                mx0 = fmaxf(mx0, fmaxf(sacc[nt][0], sacc[nt][1]));
                mx1 = fmaxf(mx1, fmaxf(sacc[nt][2], sacc[nt][3]));
            }
            mx0 = fmaxf(mx0, __shfl_xor_sync(0xffffffff, mx0, 1));
            mx0 = fmaxf(mx0, __shfl_xor_sync(0xffffffff, mx0, 2));
            mx1 = fmaxf(mx1, __shfl_xor_sync(0xffffffff, mx1, 1));
            mx1 = fmaxf(mx1, __shfl_xor_sync(0xffffffff, mx1, 2));

            float mn0 = fmaxf(m0s, mx0), mn1 = fmaxf(m1s, mx1);
            float al0 = __expf(m0s - mn0), al1 = __expf(m1s - mn1);
            m0s = mn0; m1s = mn1;

            // exp + pack P into f16 A-fragments (m16n8k16): chunk c covers nt=2c,2c+1
            uint32_t pb[4][4];
            float sum0 = 0.f, sum1 = 0.f;
            #pragma unroll
            for (int nt = 0; nt < 8; nt++) {
                float p0 = __expf(sacc[nt][0] - mn0);
                float p1 = __expf(sacc[nt][1] - mn0);
                float p2 = __expf(sacc[nt][2] - mn1);
                float p3 = __expf(sacc[nt][3] - mn1);
                sum0 += p0 + p1; sum1 += p2 + p3;
                int c = nt >> 1;
                if ((nt & 1) == 0) {
                    pb[c][0] = pk_f16x2(p0, p1);
                    pb[c][1] = pk_f16x2(p2, p3);
                } else {
                    pb[c][2] = pk_f16x2(p0, p1);
                    pb[c][3] = pk_f16x2(p2, p3);
                }
            }
            sum0 += __shfl_xor_sync(0xffffffff, sum0, 1);
            sum0 += __shfl_xor_sync(0xffffffff, sum0, 2);
            sum1 += __shfl_xor_sync(0xffffffff, sum1, 1);
            sum1 += __shfl_xor_sync(0xffffffff, sum1, 2);
            l0s = l0s * al0 + sum0;
            l1s = l1s * al1 + sum1;

            #pragma unroll
            for (int nt = 0; nt < 8; nt++) {
                acc_o[nt][0] *= al0; acc_o[nt][1] *= al0;
                acc_o[nt][2] *= al1; acc_o[nt][3] *= al1;
            }

            // O += P @ V : f16 m16n8k16, P from registers, V from Vc
            #pragma unroll
            for (int c = 0; c < 4; c++) {
                #pragma unroll
                for (int nt = 0; nt < 8; nt++) {
                    uint32_t b[2];
                    b[0] = Vc[(8 * c + t) * VPS + nt * 8 + g];
                    b[1] = Vc[(8 * c + 4 + t) * VPS + nt * 8 + g];
                    MMA_F16(acc_o[nt], pb[c], b);
                }
            }
        }

        CP_WAIT0();
        __syncthreads();
    }

    // Epilogue: y[b, row, h*64 + d]
    const int h = bh & (HH - 1);
    const int b = bh >> 4;
    const float inv0 = 1.f / l0s, inv1 = 1.f / l1s;
    size_t row0 = (size_t)b * TT + mb * 128 + r0;
    #pragma unroll
    for (int nt = 0; nt < 8; nt++) {
        int col = h * DD + nt * 8 + 2 * t;
        float2 o0 = { acc_o[nt][0] * inv0, acc_o[nt][1] * inv0 };
        float2 o1 = { acc_o[nt][2] * inv1, acc_o[nt][3] * inv1 };
        *(float2*)(g_y + row0 * CC + col) = o0;
        *(float2*)(g_y + (row0 + 8) * CC + col) = o1;
    }
}

// ---------------------------------------------------------------------------
// Launch
// ---------------------------------------------------------------------------
extern "C" void kernel_launch(void* const* d_in, const int* in_sizes, int n_in,
                              void* d_out, int out_size)
{
    const float* x       = (const float*)d_in[0];
    const float* W_share = (const float*)d_in[1];
    const float* b_share = (const float*)d_in[2];
    const float* Wq      = (const float*)d_in[3];
    const float* bq      = (const float*)d_in[4];
    const float* Wk      = (const float*)d_in[5];
    const float* bk      = (const float*)d_in[6];
    const float* Wv      = (const float*)d_in[7];
    const float* bv      = (const float*)d_in[8];
    const float* Wo      = (const float*)d_in[9];
    const float* bo      = (const float*)d_in[10];
    float* out = (float*)d_out;

    float *p_share, *p_q, *p_k, *p_v, *p_y;
    float *p_WqT, *p_WkT, *p_WvT, *p_WoT;
    cudaGetSymbolAddress((void**)&p_share, g_share);
    cudaGetSymbolAddress((void**)&p_q, g_q);
    cudaGetSymbolAddress((void**)&p_k, g_k);
    cudaGetSymbolAddress((void**)&p_v, g_v);
    cudaGetSymbolAddress((void**)&p_y, g_y);
    cudaGetSymbolAddress((void**)&p_WqT, g_WqT);
    cudaGetSymbolAddress((void**)&p_WkT, g_WkT);
    cudaGetSymbolAddress((void**)&p_WvT, g_WvT);
    cudaGetSymbolAddress((void**)&p_WoT, g_WoT);

    dim3 blk(256);
    dim3 tblk(32, 8);

    // Weight transposes (K-major B operand for mma row.col)
    transpose_kernel<<<dim3(768 / 32, 1024 / 32), tblk>>>(Wq, p_WqT, 1024, 768);
    transpose_kernel<<<dim3(768 / 32, 1024 / 32), tblk>>>(Wk, p_WkT, 1024, 768);
    transpose_kernel<<<dim3(1024 / 32, 1024 / 32), tblk>>>(Wv, p_WvT, 1024, 1024);
    transpose_kernel<<<dim3(1024 / 32, 1024 / 32), tblk>>>(Wo, p_WoT, 1024, 1024);

    // Shared projection (SIMT, N=16) -> g_share
    gemm_bias_kernel<<<dim3(1, MM / 64), blk>>>(x, W_share, b_share, p_share,
                                                MM, SHARED_D, CC);

    // Broadcast shared dims into q/k head layout (scaled/rounded)
    broadcast_share_kernel<<<(BH * TT * 4) / 256, blk>>>();

    // Tensor-core projections with fused scatter epilogues
    gemm_tf32mma<<<dim3(6, MM / 128), blk>>>(x, p_WqT, bq, p_q, 768, 3);
    gemm_tf32mma<<<dim3(6, MM / 128), blk>>>(x, p_WkT, bk, p_k, 768, 1);
    gemm_tf32mma<<<dim3(8, MM / 128), blk>>>(x, p_WvT, bv, p_v, 1024, 2);

    // Flash attention (double-buffered cp.async K, f16 PV, register P)
    const int FA_SMEM = (128 * FAS + 2 * 64 * FAS + 2 * 32 * VPS) * 4;  // 88064
    cudaFuncSetAttribute(flash_attn_mma, cudaFuncAttributeMaxDynamicSharedMemorySize, FA_SMEM);
    flash_attn_mma<<<dim3(TT / 128, BH), blk, FA_SMEM>>>();

    // Output projection (linear epilogue)
    gemm_tf32mma<<<dim3(8, MM / 128), blk>>>(p_y, p_WoT, bo, out, 1024, 0);

    (void)in_sizes; (void)n_in; (void)out_size;
}